// round 7
// baseline (speedup 1.0000x reference)
#include <cuda_runtime.h>
#include <math.h>

// ---------------------------------------------------------------------------
// 3-layer LSTM (H=51) + linear(2) head, B=1024, T=2048, persistent kernel.
// 128 CTAs x 408 threads. Thread (j, gp, b4, kh): unit j, gate pair gp
// (gp0 -> gates i,g ; gp1 -> gates f,o), batch quad b4, k-half kh.
// Packed fma.rn.f32x2 over k-pairs; activations [batch][k] stride 60.
// kh halves combine via shfl_xor(1); gate halves via shfl_xor(4) with the
// mB trick (tanh = 2*sig(2x)-1). L0 recurrent weights cached in registers.
// 3 __syncthreads per timestep.
// ---------------------------------------------------------------------------

#define Hn    51
#define NG    204
#define Tn    2048
#define NBb   8
#define NCTA  128
#define NT    408
#define CHUNK 16
#define ABST  60                 // act batch-row stride (floats)
#define HBUF  (8 * ABST)         // 480 floats per (layer,buf)

// SMEM float offsets
#define O_WHH0 0
#define O_WIH1 10608
#define O_WHH1 21216
#define O_WIH2 31824
#define O_WHH2 42432
#define O_BIAS 53040             // [3][204]
#define O_WLIN 53652             // [2][52]
#define O_BLIN 53756             // 2 (+2 pad)
#define O_H    53760             // 6 * 480 = 2880
#define O_XS   (O_H + 6 * HBUF)  // 56640 : [16][16]
#define SM_FLOATS (O_XS + CHUNK * 16)   // 56896
#define SM_BYTES  (SM_FLOATS * 4)       // 227584 <= 232448

typedef unsigned long long ull;

__device__ __forceinline__ void f2(ull& a, ull w, ull v) {
    asm("fma.rn.f32x2 %0, %1, %2, %0;" : "+l"(a) : "l"(w), "l"(v));
}
__device__ __forceinline__ float hadd(ull v) {
    unsigned lo, hi;
    asm("mov.b64 {%0,%1}, %2;" : "=r"(lo), "=r"(hi) : "l"(v));
    return __uint_as_float(lo) + __uint_as_float(hi);
}
__device__ __forceinline__ float fsig(float x) {
    return __fdividef(1.0f, 1.0f + __expf(-x));
}
__device__ __forceinline__ float ftanh(float x) {
    return __fdividef(2.0f, 1.0f + __expf(-2.0f * x)) - 1.0f;
}

// acc[base+b] (u64 k-pair lanes) += w (2 k) * act_b (2 k), for 4 batches
#define FMA2B4(base, wreg, a0, a1, a2, a3)                                    \
    f2(acc[(base)+0], (wreg).x, (a0).x); f2(acc[(base)+0], (wreg).y, (a0).y); \
    f2(acc[(base)+1], (wreg).x, (a1).x); f2(acc[(base)+1], (wreg).y, (a1).y); \
    f2(acc[(base)+2], (wreg).x, (a2).x); f2(acc[(base)+2], (wreg).y, (a2).y); \
    f2(acc[(base)+3], (wreg).x, (a3).x); f2(acc[(base)+3], (wreg).y, (a3).y);

// combine kh pair for gate slot g (0=A,1=B) -> own 2 batches r0, r1
#define CMB(g, r0, r1)                                                \
    {                                                                 \
        float oa = kh ? s[(g)*4+2] : s[(g)*4+0];                      \
        float ob = kh ? s[(g)*4+3] : s[(g)*4+1];                      \
        float xa = kh ? s[(g)*4+0] : s[(g)*4+2];                      \
        float xb = kh ? s[(g)*4+1] : s[(g)*4+3];                      \
        r0 = oa + __shfl_xor_sync(mask, xa, 1);                       \
        r1 = ob + __shfl_xor_sync(mask, xb, 1);                       \
    }

// gate-pair tail: gp0 has (i,g), gp1 has (f,o); gp1 owns c, stores h.
// pA0/pA1, pB0/pB1 are full biased pre-acts for this thread's 2 batches.
#define GTAIL(cc0, cc1, hd)                                                   \
    do {                                                                      \
        float sA0 = fsig(pA0), sA1 = fsig(pA1);                               \
        float vB0 = __fdividef(mB, 1.0f + __expf(-mB * pB0)) - mBm1;          \
        float vB1 = __fdividef(mB, 1.0f + __expf(-mB * pB1)) - mBm1;          \
        float u0 = __shfl_xor_sync(mask, sA0 * vB0, 4);                       \
        float u1 = __shfl_xor_sync(mask, sA1 * vB1, 4);                       \
        if (gp) {                                                             \
            cc0 = sA0 * cc0 + u0;                                             \
            cc1 = sA1 * cc1 + u1;                                             \
            (hd)[ob0 * ABST + j] = vB0 * ftanh(cc0);                          \
            (hd)[ob1 * ABST + j] = vB1 * ftanh(cc1);                          \
        }                                                                     \
    } while (0)

// two-matrix dot for 2 gate rows: acc[0..3] += wA-row, acc[4..7] += wB-row
__device__ __forceinline__ void dot2g(const float* __restrict__ wiA,
                                      const float* __restrict__ wiB,
                                      const float* __restrict__ whA,
                                      const float* __restrict__ whB,
                                      const float* __restrict__ xa,
                                      const float* __restrict__ ha,
                                      ull* acc)
{
    #pragma unroll
    for (int c = 0; c < 7; c++) {
        ulonglong2 wA = *(const ulonglong2*)(wiA + c * 4);
        ulonglong2 wB = *(const ulonglong2*)(wiB + c * 4);
        ulonglong2 a0 = *(const ulonglong2*)(xa + 0 * ABST + c * 4);
        ulonglong2 a1 = *(const ulonglong2*)(xa + 1 * ABST + c * 4);
        ulonglong2 a2 = *(const ulonglong2*)(xa + 2 * ABST + c * 4);
        ulonglong2 a3 = *(const ulonglong2*)(xa + 3 * ABST + c * 4);
        FMA2B4(0, wA, a0, a1, a2, a3);
        FMA2B4(4, wB, a0, a1, a2, a3);
        ulonglong2 vA = *(const ulonglong2*)(whA + c * 4);
        ulonglong2 vB = *(const ulonglong2*)(whB + c * 4);
        ulonglong2 h0 = *(const ulonglong2*)(ha + 0 * ABST + c * 4);
        ulonglong2 h1 = *(const ulonglong2*)(ha + 1 * ABST + c * 4);
        ulonglong2 h2 = *(const ulonglong2*)(ha + 2 * ABST + c * 4);
        ulonglong2 h3 = *(const ulonglong2*)(ha + 3 * ABST + c * 4);
        FMA2B4(0, vA, h0, h1, h2, h3);
        FMA2B4(4, vB, h0, h1, h2, h3);
    }
}

__global__ void __launch_bounds__(NT, 1) lstm_pers(
    const float* __restrict__ xin,  const float* __restrict__ tin,
    const float* __restrict__ Wih0, const float* __restrict__ Whh0,
    const float* __restrict__ bih0, const float* __restrict__ bhh0,
    const float* __restrict__ Wih1, const float* __restrict__ Whh1,
    const float* __restrict__ bih1, const float* __restrict__ bhh1,
    const float* __restrict__ Wih2, const float* __restrict__ Whh2,
    const float* __restrict__ bih2, const float* __restrict__ bhh2,
    const float* __restrict__ Wlin, const float* __restrict__ blin,
    float* __restrict__ out)
{
    extern __shared__ float sm[];
    const int tid   = threadIdx.x;
    const int bbase = blockIdx.x * NBb;

    // ---- one-time staging: rows padded to 52 floats (col 51 = 0) ----
    {
        const float* srcs[5] = {Whh0, Wih1, Whh1, Wih2, Whh2};
        const int    dsts[5] = {O_WHH0, O_WIH1, O_WHH1, O_WIH2, O_WHH2};
        for (int w = 0; w < 5; w++) {
            const float* s = srcs[w];
            float*       d = sm + dsts[w];
            for (int i = tid; i < NG * 52; i += NT) {
                int r = i / 52, k = i - r * 52;
                d[i] = (k < Hn) ? s[r * Hn + k] : 0.0f;
            }
        }
    }
    for (int i = tid; i < NG; i += NT) {
        sm[O_BIAS + i]          = bih0[i] + bhh0[i];
        sm[O_BIAS + NG + i]     = bih1[i] + bhh1[i];
        sm[O_BIAS + 2 * NG + i] = bih2[i] + bhh2[i];
    }
    for (int i = tid; i < 2 * 52; i += NT) {
        int r = i / 52, k = i - r * 52;
        sm[O_WLIN + i] = (k < Hn) ? Wlin[r * Hn + k] : 0.0f;
    }
    if (tid < 2) sm[O_BLIN + tid] = blin[tid];
    for (int i = tid; i < 6 * HBUF; i += NT) sm[O_H + i] = 0.0f;
    __syncthreads();

    const int j  = tid >> 3;          // 0..50
    const int gp = (tid >> 2) & 1;    // 0: gates (i,g)   1: gates (f,o)
    const int b4 = (tid >> 1) & 1;    // batch quad
    const int kh = tid & 1;           // k half
    const unsigned mask = (tid >= 384) ? 0x00FFFFFFu : 0xFFFFFFFFu;
    const int ko = kh * 28;
    const float mB   = gp ? 1.0f : 2.0f;   // gp0: tanh via 2*sig(2x)-1
    const float mBm1 = mB - 1.0f;

    const int rowA = (gp ? 1 : 0) * Hn + j;   // f : i
    const int rowB = (gp ? 3 : 2) * Hn + j;   // o : g

    // biases (added after kh combine)
    const float bA0 = sm[O_BIAS + rowA],          bB0 = sm[O_BIAS + rowB];
    const float bA1 = sm[O_BIAS + NG + rowA],     bB1 = sm[O_BIAS + NG + rowB];
    const float bA2 = sm[O_BIAS + 2*NG + rowA],   bB2 = sm[O_BIAS + 2*NG + rowB];

    // L0 input weights (2 cols)
    const float wxA0 = Wih0[rowA*2], wxA1 = Wih0[rowA*2 + 1];
    const float wxB0 = Wih0[rowB*2], wxB1 = Wih0[rowB*2 + 1];

    // layer-0 recurrent weights cached in registers (constant over T)
    ulonglong2 w0r[2][7];
    #pragma unroll
    for (int c = 0; c < 7; c++) {
        w0r[0][c] = *(const ulonglong2*)(sm + O_WHH0 + rowA*52 + ko + c*4);
        w0r[1][c] = *(const ulonglong2*)(sm + O_WHH0 + rowB*52 + ko + c*4);
    }

    const float* wiA1 = sm + O_WIH1 + rowA * 52 + ko;
    const float* wiB1 = sm + O_WIH1 + rowB * 52 + ko;
    const float* whA1 = sm + O_WHH1 + rowA * 52 + ko;
    const float* whB1 = sm + O_WHH1 + rowB * 52 + ko;
    const float* wiA2 = sm + O_WIH2 + rowA * 52 + ko;
    const float* wiB2 = sm + O_WIH2 + rowB * 52 + ko;
    const float* whA2 = sm + O_WHH2 + rowA * 52 + ko;
    const float* whB2 = sm + O_WHH2 + rowB * 52 + ko;

    const int aoff = b4 * 4 * ABST + ko;   // act base offset within a buffer
    const int ob0  = b4 * 4 + kh * 2;      // own global batch indices
    const int ob1  = ob0 + 1;

    float c00 = 0, c01 = 0, c10 = 0, c11 = 0, c20 = 0, c21 = 0;

    for (int t = 0; t < Tn; t++) {
        const int tc = t & (CHUNK - 1);
        if (tc == 0) {
            for (int i = tid; i < CHUNK * 16; i += NT) {
                int tt = i >> 4, col = i & 15;
                float v;
                if (col < 8) v = xin[(size_t)(bbase + col) * Tn + t + tt];
                else         v = tin[(size_t)(bbase + col - 8) * Tn + t + tt];
                sm[O_XS + i] = v;
            }
            __syncthreads();
        }
        const int bc = t & 1, bo = bc ^ 1;

        // ---------------- layer 0 ----------------
        {
            ull acc[8];
            #pragma unroll
            for (int ii = 0; ii < 8; ii++) acc[ii] = 0ull;
            const float* ha = sm + O_H + (0 + bo) * HBUF + aoff;
            #pragma unroll
            for (int c = 0; c < 7; c++) {
                ulonglong2 h0 = *(const ulonglong2*)(ha + 0 * ABST + c * 4);
                ulonglong2 h1 = *(const ulonglong2*)(ha + 1 * ABST + c * 4);
                ulonglong2 h2 = *(const ulonglong2*)(ha + 2 * ABST + c * 4);
                ulonglong2 h3 = *(const ulonglong2*)(ha + 3 * ABST + c * 4);
                FMA2B4(0, w0r[0][c], h0, h1, h2, h3);
                FMA2B4(4, w0r[1][c], h0, h1, h2, h3);
            }
            float s[8];
            #pragma unroll
            for (int ii = 0; ii < 8; ii++) s[ii] = hadd(acc[ii]);
            float pA0, pA1, pB0, pB1;
            CMB(0, pA0, pA1); CMB(1, pB0, pB1);
            float xi0 = sm[O_XS + tc*16 + ob0],     xi1 = sm[O_XS + tc*16 + ob1];
            float ti0 = sm[O_XS + tc*16 + 8 + ob0], ti1 = sm[O_XS + tc*16 + 8 + ob1];
            pA0 += bA0 + wxA0*xi0 + wxA1*ti0;  pA1 += bA0 + wxA0*xi1 + wxA1*ti1;
            pB0 += bB0 + wxB0*xi0 + wxB1*ti0;  pB1 += bB0 + wxB0*xi1 + wxB1*ti1;
            GTAIL(c00, c01, sm + O_H + (0 + bc) * HBUF);
        }
        __syncthreads();

        // ---------------- layer 1 ----------------
        {
            ull acc[8];
            #pragma unroll
            for (int ii = 0; ii < 8; ii++) acc[ii] = 0ull;
            dot2g(wiA1, wiB1, whA1, whB1,
                  sm + O_H + (0 + bc) * HBUF + aoff,
                  sm + O_H + (2 + bo) * HBUF + aoff, acc);
            float s[8];
            #pragma unroll
            for (int ii = 0; ii < 8; ii++) s[ii] = hadd(acc[ii]);
            float pA0, pA1, pB0, pB1;
            CMB(0, pA0, pA1); CMB(1, pB0, pB1);
            pA0 += bA1; pA1 += bA1; pB0 += bB1; pB1 += bB1;
            GTAIL(c10, c11, sm + O_H + (2 + bc) * HBUF);
        }
        __syncthreads();

        // ---------------- layer 2 ----------------
        {
            ull acc[8];
            #pragma unroll
            for (int ii = 0; ii < 8; ii++) acc[ii] = 0ull;
            dot2g(wiA2, wiB2, whA2, whB2,
                  sm + O_H + (2 + bc) * HBUF + aoff,
                  sm + O_H + (4 + bo) * HBUF + aoff, acc);
            float s[8];
            #pragma unroll
            for (int ii = 0; ii < 8; ii++) s[ii] = hadd(acc[ii]);
            float pA0, pA1, pB0, pB1;
            CMB(0, pA0, pA1); CMB(1, pB0, pB1);
            pA0 += bA2; pA1 += bA2; pB0 += bB2; pB1 += bB2;
            GTAIL(c20, c21, sm + O_H + (4 + bc) * HBUF);
        }
        __syncthreads();

        // ---------------- linear head + softplus ----------------
        if (tid < 16) {
            int bb = tid >> 1, o = tid & 1;
            const float* hh = sm + O_H + (4 + bc) * HBUF + bb * ABST;
            const float* w  = sm + O_WLIN + o * 52;
            float ssum = sm[O_BLIN + o];
            #pragma unroll
            for (int k = 0; k < Hn; k++) ssum += w[k] * hh[k];
            if (o) ssum = (ssum > 30.0f) ? ssum : log1pf(expf(ssum));
            out[(((size_t)(bbase + bb)) * Tn + (size_t)t) * 2 + o] = ssum;
        }
        // (4,bc) next rewritten at t+2's L2, >= 5 barriers away — safe.
    }
}

extern "C" void kernel_launch(void* const* d_in, const int* in_sizes, int n_in,
                              void* d_out, int out_size)
{
    (void)in_sizes; (void)n_in; (void)out_size;
    cudaFuncSetAttribute(lstm_pers, cudaFuncAttributeMaxDynamicSharedMemorySize,
                         SM_BYTES);
    lstm_pers<<<NCTA, NT, SM_BYTES>>>(
        (const float*)d_in[0],  (const float*)d_in[1],
        (const float*)d_in[2],  (const float*)d_in[3],
        (const float*)d_in[4],  (const float*)d_in[5],
        (const float*)d_in[6],  (const float*)d_in[7],
        (const float*)d_in[8],  (const float*)d_in[9],
        (const float*)d_in[10], (const float*)d_in[11],
        (const float*)d_in[12], (const float*)d_in[13],
        (const float*)d_in[14], (const float*)d_in[15],
        (float*)d_out);
}

// round 8
// speedup vs baseline: 1.3909x; 1.3909x over previous
#include <cuda_runtime.h>
#include <math.h>

// ---------------------------------------------------------------------------
// 3-layer LSTM (H=51) + linear(2) head, B=1024, T=2048, persistent kernel.
// 128 CTAs x 204 threads. Thread (j, b4, kh): unit j (all 4 gates), batch
// quad b4, k-half kh. Packed fma.rn.f32x2 over k-pairs; weights read from
// SMEM as u64 pairs (NO register weight cache -> no spills); activations
// stored [batch][k] (stride 60). kh pair combined via shfl_xor(1).
// 3 __syncthreads per timestep.
// ---------------------------------------------------------------------------

#define Hn    51
#define NG    204
#define Tn    2048
#define NBb   8
#define NCTA  128
#define NT    204
#define CHUNK 16
#define ABST  60                 // act batch-row stride (floats)
#define HBUF  (8 * ABST)         // 480 floats per (layer,buf)
#define GOFF  (Hn * 52)          // 2652: gate-row stride in a weight matrix

// SMEM float offsets
#define O_WHH0 0
#define O_WIH1 10608
#define O_WHH1 21216
#define O_WIH2 31824
#define O_WHH2 42432
#define O_BIAS 53040             // [3][204]
#define O_WLIN 53652             // [2][52]
#define O_BLIN 53756             // 2 (+2 pad)
#define O_H    53760             // 6 * 480 = 2880
#define O_XS   (O_H + 6 * HBUF)  // 56640 : [16][16]
#define SM_FLOATS (O_XS + CHUNK * 16)   // 56896
#define SM_BYTES  (SM_FLOATS * 4)       // 227584 <= 232448

typedef unsigned long long ull;

__device__ __forceinline__ void f2(ull& a, ull w, ull v) {
    asm("fma.rn.f32x2 %0, %1, %2, %0;" : "+l"(a) : "l"(w), "l"(v));
}
__device__ __forceinline__ float hadd(ull v) {
    unsigned lo, hi;
    asm("mov.b64 {%0,%1}, %2;" : "=r"(lo), "=r"(hi) : "l"(v));
    return __uint_as_float(lo) + __uint_as_float(hi);
}
__device__ __forceinline__ float fsig(float x) {
    return __fdividef(1.0f, 1.0f + __expf(-x));
}
__device__ __forceinline__ float ftanh(float x) {
    return __fdividef(2.0f, 1.0f + __expf(-2.0f * x)) - 1.0f;
}

// acc[base+b] (u64 k-pair lanes) += w (2 k) * act_b (2 k), for 4 batches
#define FMA2BLK(base, wreg, a0, a1, a2, a3)                          \
    f2(acc[(base)+0], (wreg).x, (a0).x); f2(acc[(base)+0], (wreg).y, (a0).y); \
    f2(acc[(base)+1], (wreg).x, (a1).x); f2(acc[(base)+1], (wreg).y, (a1).y); \
    f2(acc[(base)+2], (wreg).x, (a2).x); f2(acc[(base)+2], (wreg).y, (a2).y); \
    f2(acc[(base)+3], (wreg).x, (a3).x); f2(acc[(base)+3], (wreg).y, (a3).y);

// combine kh pair for gate g -> full pre-acts r0, r1 for own 2 batches
#define CMB(g, r0, r1)                                                \
    {                                                                 \
        float oa = kh ? s[(g)*4+2] : s[(g)*4+0];                      \
        float ob = kh ? s[(g)*4+3] : s[(g)*4+1];                      \
        float xa = kh ? s[(g)*4+0] : s[(g)*4+2];                      \
        float xb = kh ? s[(g)*4+1] : s[(g)*4+3];                      \
        r0 = oa + __shfl_xor_sync(mask, xa, 1);                       \
        r1 = ob + __shfl_xor_sync(mask, xb, 1);                       \
    }

// single-matrix dot: wh @ h-act, 7 k-chunks of 4 (layer-0 recurrent part)
__device__ __forceinline__ void dot1(const float* __restrict__ wh,
                                     const float* __restrict__ ha,
                                     ull* acc)
{
    #pragma unroll
    for (int c = 0; c < 7; c++) {
        ulonglong2 v0 = *(const ulonglong2*)(wh + 0 * GOFF + c * 4);
        ulonglong2 v1 = *(const ulonglong2*)(wh + 1 * GOFF + c * 4);
        ulonglong2 v2 = *(const ulonglong2*)(wh + 2 * GOFF + c * 4);
        ulonglong2 v3 = *(const ulonglong2*)(wh + 3 * GOFF + c * 4);
        ulonglong2 h0 = *(const ulonglong2*)(ha + 0 * ABST + c * 4);
        ulonglong2 h1 = *(const ulonglong2*)(ha + 1 * ABST + c * 4);
        ulonglong2 h2 = *(const ulonglong2*)(ha + 2 * ABST + c * 4);
        ulonglong2 h3 = *(const ulonglong2*)(ha + 3 * ABST + c * 4);
        FMA2BLK(0,  v0, h0, h1, h2, h3);
        FMA2BLK(4,  v1, h0, h1, h2, h3);
        FMA2BLK(8,  v2, h0, h1, h2, h3);
        FMA2BLK(12, v3, h0, h1, h2, h3);
    }
}

// two-matrix dot: wi @ x-act + wh @ h-act, 7 k-chunks of 4
__device__ __forceinline__ void dot2(const float* __restrict__ wi,
                                     const float* __restrict__ wh,
                                     const float* __restrict__ xa,
                                     const float* __restrict__ ha,
                                     ull* acc)
{
    #pragma unroll
    for (int c = 0; c < 7; c++) {
        ulonglong2 w0 = *(const ulonglong2*)(wi + 0 * GOFF + c * 4);
        ulonglong2 w1 = *(const ulonglong2*)(wi + 1 * GOFF + c * 4);
        ulonglong2 w2 = *(const ulonglong2*)(wi + 2 * GOFF + c * 4);
        ulonglong2 w3 = *(const ulonglong2*)(wi + 3 * GOFF + c * 4);
        ulonglong2 a0 = *(const ulonglong2*)(xa + 0 * ABST + c * 4);
        ulonglong2 a1 = *(const ulonglong2*)(xa + 1 * ABST + c * 4);
        ulonglong2 a2 = *(const ulonglong2*)(xa + 2 * ABST + c * 4);
        ulonglong2 a3 = *(const ulonglong2*)(xa + 3 * ABST + c * 4);
        FMA2BLK(0,  w0, a0, a1, a2, a3);
        FMA2BLK(4,  w1, a0, a1, a2, a3);
        FMA2BLK(8,  w2, a0, a1, a2, a3);
        FMA2BLK(12, w3, a0, a1, a2, a3);
        ulonglong2 v0 = *(const ulonglong2*)(wh + 0 * GOFF + c * 4);
        ulonglong2 v1 = *(const ulonglong2*)(wh + 1 * GOFF + c * 4);
        ulonglong2 v2 = *(const ulonglong2*)(wh + 2 * GOFF + c * 4);
        ulonglong2 v3 = *(const ulonglong2*)(wh + 3 * GOFF + c * 4);
        ulonglong2 h0 = *(const ulonglong2*)(ha + 0 * ABST + c * 4);
        ulonglong2 h1 = *(const ulonglong2*)(ha + 1 * ABST + c * 4);
        ulonglong2 h2 = *(const ulonglong2*)(ha + 2 * ABST + c * 4);
        ulonglong2 h3 = *(const ulonglong2*)(ha + 3 * ABST + c * 4);
        FMA2BLK(0,  v0, h0, h1, h2, h3);
        FMA2BLK(4,  v1, h0, h1, h2, h3);
        FMA2BLK(8,  v2, h0, h1, h2, h3);
        FMA2BLK(12, v3, h0, h1, h2, h3);
    }
}

__global__ void __launch_bounds__(NT, 1) lstm_pers(
    const float* __restrict__ xin,  const float* __restrict__ tin,
    const float* __restrict__ Wih0, const float* __restrict__ Whh0,
    const float* __restrict__ bih0, const float* __restrict__ bhh0,
    const float* __restrict__ Wih1, const float* __restrict__ Whh1,
    const float* __restrict__ bih1, const float* __restrict__ bhh1,
    const float* __restrict__ Wih2, const float* __restrict__ Whh2,
    const float* __restrict__ bih2, const float* __restrict__ bhh2,
    const float* __restrict__ Wlin, const float* __restrict__ blin,
    float* __restrict__ out)
{
    extern __shared__ float sm[];
    const int tid   = threadIdx.x;
    const int bbase = blockIdx.x * NBb;

    // ---- one-time staging: rows padded to 52 floats (col 51 = 0) ----
    {
        const float* srcs[5] = {Whh0, Wih1, Whh1, Wih2, Whh2};
        const int    dsts[5] = {O_WHH0, O_WIH1, O_WHH1, O_WIH2, O_WHH2};
        for (int w = 0; w < 5; w++) {
            const float* s = srcs[w];
            float*       d = sm + dsts[w];
            for (int i = tid; i < NG * 52; i += NT) {
                int r = i / 52, k = i - r * 52;
                d[i] = (k < Hn) ? s[r * Hn + k] : 0.0f;
            }
        }
    }
    for (int i = tid; i < NG; i += NT) {
        sm[O_BIAS + i]          = bih0[i] + bhh0[i];
        sm[O_BIAS + NG + i]     = bih1[i] + bhh1[i];
        sm[O_BIAS + 2 * NG + i] = bih2[i] + bhh2[i];
    }
    for (int i = tid; i < 2 * 52; i += NT) {
        int r = i / 52, k = i - r * 52;
        sm[O_WLIN + i] = (k < Hn) ? Wlin[r * Hn + k] : 0.0f;
    }
    if (tid < 2) sm[O_BLIN + tid] = blin[tid];
    for (int i = tid; i < 6 * HBUF; i += NT) sm[O_H + i] = 0.0f;
    __syncthreads();

    const int j  = tid >> 2;          // 0..50
    const int b4 = (tid >> 1) & 1;    // batch quad
    const int kh = tid & 1;           // k half
    const unsigned mask = (tid >= 192) ? 0x00000FFFu : 0xFFFFFFFFu;
    const int ko = kh * 28;

    // biases (added after kh combine, once per thread's own batches)
    const float bI0 = sm[O_BIAS + 0*Hn + j],          bF0 = sm[O_BIAS + 1*Hn + j];
    const float bG0 = sm[O_BIAS + 2*Hn + j],          bO0 = sm[O_BIAS + 3*Hn + j];
    const float bI1 = sm[O_BIAS + NG + 0*Hn + j],     bF1 = sm[O_BIAS + NG + 1*Hn + j];
    const float bG1 = sm[O_BIAS + NG + 2*Hn + j],     bO1 = sm[O_BIAS + NG + 3*Hn + j];
    const float bI2 = sm[O_BIAS + 2*NG + 0*Hn + j],   bF2 = sm[O_BIAS + 2*NG + 1*Hn + j];
    const float bG2 = sm[O_BIAS + 2*NG + 2*Hn + j],   bO2 = sm[O_BIAS + 2*NG + 3*Hn + j];

    // L0 input weights (2 cols)
    const float wxI0 = Wih0[(0*Hn + j)*2], wxI1 = Wih0[(0*Hn + j)*2 + 1];
    const float wxF0 = Wih0[(1*Hn + j)*2], wxF1 = Wih0[(1*Hn + j)*2 + 1];
    const float wxG0 = Wih0[(2*Hn + j)*2], wxG1 = Wih0[(2*Hn + j)*2 + 1];
    const float wxO0 = Wih0[(3*Hn + j)*2], wxO1 = Wih0[(3*Hn + j)*2 + 1];

    const float* wh0 = sm + O_WHH0 + j * 52 + ko;
    const float* wi1 = sm + O_WIH1 + j * 52 + ko;
    const float* wh1 = sm + O_WHH1 + j * 52 + ko;
    const float* wi2 = sm + O_WIH2 + j * 52 + ko;
    const float* wh2 = sm + O_WHH2 + j * 52 + ko;

    const int aoff = b4 * 4 * ABST + ko;   // act base offset within a buffer
    const int ob0  = b4 * 4 + kh * 2;      // own global batch indices
    const int ob1  = ob0 + 1;

    float c00 = 0, c01 = 0, c10 = 0, c11 = 0, c20 = 0, c21 = 0;

    for (int t = 0; t < Tn; t++) {
        const int tc = t & (CHUNK - 1);
        if (tc == 0) {
            for (int i = tid; i < CHUNK * 16; i += NT) {
                int tt = i >> 4, col = i & 15;
                float v;
                if (col < 8) v = xin[(size_t)(bbase + col) * Tn + t + tt];
                else         v = tin[(size_t)(bbase + col - 8) * Tn + t + tt];
                sm[O_XS + i] = v;
            }
            __syncthreads();
        }
        const int bc = t & 1, bo = bc ^ 1;

        // ---------------- layer 0 ----------------
        {
            ull acc[16];
            #pragma unroll
            for (int ii = 0; ii < 16; ii++) acc[ii] = 0ull;
            dot1(wh0, sm + O_H + (0 + bo) * HBUF + aoff, acc);
            float s[16];
            #pragma unroll
            for (int ii = 0; ii < 16; ii++) s[ii] = hadd(acc[ii]);
            float pi0, pi1, pf0, pf1, pg0, pg1, po0, po1;
            CMB(0, pi0, pi1); CMB(1, pf0, pf1);
            CMB(2, pg0, pg1); CMB(3, po0, po1);
            float x0 = sm[O_XS + tc*16 + ob0],     x1 = sm[O_XS + tc*16 + ob1];
            float u0 = sm[O_XS + tc*16 + 8 + ob0], u1 = sm[O_XS + tc*16 + 8 + ob1];
            pi0 += bI0 + wxI0*x0 + wxI1*u0;  pi1 += bI0 + wxI0*x1 + wxI1*u1;
            pf0 += bF0 + wxF0*x0 + wxF1*u0;  pf1 += bF0 + wxF0*x1 + wxF1*u1;
            pg0 += bG0 + wxG0*x0 + wxG1*u0;  pg1 += bG0 + wxG0*x1 + wxG1*u1;
            po0 += bO0 + wxO0*x0 + wxO1*u0;  po1 += bO0 + wxO0*x1 + wxO1*u1;
            float ig0 = fsig(pi0), ig1 = fsig(pi1);
            float fg0 = fsig(pf0), fg1 = fsig(pf1);
            float gg0 = ftanh(pg0), gg1 = ftanh(pg1);
            float og0 = fsig(po0), og1 = fsig(po1);
            c00 = fg0*c00 + ig0*gg0;  c01 = fg1*c01 + ig1*gg1;
            float* hd = sm + O_H + (0 + bc) * HBUF;
            hd[ob0*ABST + j] = og0 * ftanh(c00);
            hd[ob1*ABST + j] = og1 * ftanh(c01);
        }
        __syncthreads();

        // ---------------- layer 1 ----------------
        {
            ull acc[16];
            #pragma unroll
            for (int ii = 0; ii < 16; ii++) acc[ii] = 0ull;
            dot2(wi1, wh1,
                 sm + O_H + (0 + bc) * HBUF + aoff,
                 sm + O_H + (2 + bo) * HBUF + aoff, acc);
            float s[16];
            #pragma unroll
            for (int ii = 0; ii < 16; ii++) s[ii] = hadd(acc[ii]);
            float pi0, pi1, pf0, pf1, pg0, pg1, po0, po1;
            CMB(0, pi0, pi1); CMB(1, pf0, pf1);
            CMB(2, pg0, pg1); CMB(3, po0, po1);
            float ig0 = fsig(pi0 + bI1), ig1 = fsig(pi1 + bI1);
            float fg0 = fsig(pf0 + bF1), fg1 = fsig(pf1 + bF1);
            float gg0 = ftanh(pg0 + bG1), gg1 = ftanh(pg1 + bG1);
            float og0 = fsig(po0 + bO1), og1 = fsig(po1 + bO1);
            c10 = fg0*c10 + ig0*gg0;  c11 = fg1*c11 + ig1*gg1;
            float* hd = sm + O_H + (2 + bc) * HBUF;
            hd[ob0*ABST + j] = og0 * ftanh(c10);
            hd[ob1*ABST + j] = og1 * ftanh(c11);
        }
        __syncthreads();

        // ---------------- layer 2 ----------------
        {
            ull acc[16];
            #pragma unroll
            for (int ii = 0; ii < 16; ii++) acc[ii] = 0ull;
            dot2(wi2, wh2,
                 sm + O_H + (2 + bc) * HBUF + aoff,
                 sm + O_H + (4 + bo) * HBUF + aoff, acc);
            float s[16];
            #pragma unroll
            for (int ii = 0; ii < 16; ii++) s[ii] = hadd(acc[ii]);
            float pi0, pi1, pf0, pf1, pg0, pg1, po0, po1;
            CMB(0, pi0, pi1); CMB(1, pf0, pf1);
            CMB(2, pg0, pg1); CMB(3, po0, po1);
            float ig0 = fsig(pi0 + bI2), ig1 = fsig(pi1 + bI2);
            float fg0 = fsig(pf0 + bF2), fg1 = fsig(pf1 + bF2);
            float gg0 = ftanh(pg0 + bG2), gg1 = ftanh(pg1 + bG2);
            float og0 = fsig(po0 + bO2), og1 = fsig(po1 + bO2);
            c20 = fg0*c20 + ig0*gg0;  c21 = fg1*c21 + ig1*gg1;
            float* hd = sm + O_H + (4 + bc) * HBUF;
            hd[ob0*ABST + j] = og0 * ftanh(c20);
            hd[ob1*ABST + j] = og1 * ftanh(c21);
        }
        __syncthreads();

        // ---------------- linear head + softplus ----------------
        if (tid < 16) {
            int bb = tid >> 1, o = tid & 1;
            const float* hh = sm + O_H + (4 + bc) * HBUF + bb * ABST;
            const float* w  = sm + O_WLIN + o * 52;
            float ssum = sm[O_BLIN + o];
            #pragma unroll
            for (int k = 0; k < Hn; k++) ssum += w[k] * hh[k];
            if (o) ssum = (ssum > 30.0f) ? ssum : log1pf(expf(ssum));
            out[(((size_t)(bbase + bb)) * Tn + (size_t)t) * 2 + o] = ssum;
        }
        // (4,bc) next rewritten at t+2's L2, >= 5 barriers away — safe.
    }
}

extern "C" void kernel_launch(void* const* d_in, const int* in_sizes, int n_in,
                              void* d_out, int out_size)
{
    (void)in_sizes; (void)n_in; (void)out_size;
    cudaFuncSetAttribute(lstm_pers, cudaFuncAttributeMaxDynamicSharedMemorySize,
                         SM_BYTES);
    lstm_pers<<<NCTA, NT, SM_BYTES>>>(
        (const float*)d_in[0],  (const float*)d_in[1],
        (const float*)d_in[2],  (const float*)d_in[3],
        (const float*)d_in[4],  (const float*)d_in[5],
        (const float*)d_in[6],  (const float*)d_in[7],
        (const float*)d_in[8],  (const float*)d_in[9],
        (const float*)d_in[10], (const float*)d_in[11],
        (const float*)d_in[12], (const float*)d_in[13],
        (const float*)d_in[14], (const float*)d_in[15],
        (float*)d_out);
}

// round 11
// speedup vs baseline: 1.4216x; 1.0221x over previous
#include <cuda_runtime.h>
#include <math.h>

// ---------------------------------------------------------------------------
// 3-layer LSTM (H=51) + linear(2) head, B=1024, T=2048, persistent kernel.
// LAYER-PIPELINED: 128 CTAs x 416 threads in 4 warp groups:
//   warps 0-3  : layer-1 group, computes t = tk-1
//   warps 4-7  : layer-2 group, computes t = tk-2
//   warps 8-11 : layer-0 group, computes t = tk
//   warp  12   : linear head,   computes t = tk-3
// ONE __syncthreads per tick. Thread (jp, b4, kh): 2 hidden units (8 gate
// rows), 4 batches, k-half; fma.rn.f32x2 k-pairs; 32 u64 accumulators.
// H padded 51->52 units (zero weights/bias => h == 0, keeps padding clean).
// (Resubmit #3 of this design; prior two attempts died to container flakes.)
// ---------------------------------------------------------------------------

#define Hn    51
#define HU    52                 // padded units
#define Tn    2048
#define NBb   8
#define NCTA  128
#define NT    416
#define ABST  60                 // act batch-row stride (floats)
#define HBUF  480                // 8 * ABST
#define MROW  52                 // floats per weight row
#define MSZ   (208 * MROW)       // 10816 floats per padded matrix
#define GST   (HU * MROW)        // 2704: gate-block stride

// SMEM float offsets
#define O_WHH0 0
#define O_WIH1 10816
#define O_WHH1 21632
#define O_WIH2 32448
#define O_WHH2 43264
#define O_BIAS 54080             // [3][208]
#define O_WLIN 54704             // [2][52]
#define O_BLIN 54808             // 2 (+2 pad)
#define O_H    54812             // 6 bufs * 480 (16B aligned: 54812*4 % 16 == 0)
#define O_XS   57692             // [16][16]
#define SM_FLOATS 57948
#define SM_BYTES  (SM_FLOATS * 4)   // 231792 <= 232448

typedef unsigned long long ull;

__device__ __forceinline__ void f2(ull& a, ull w, ull v) {
    asm("fma.rn.f32x2 %0, %1, %2, %0;" : "+l"(a) : "l"(w), "l"(v));
}
__device__ __forceinline__ float hadd(ull v) {
    unsigned lo, hi;
    asm("mov.b64 {%0,%1}, %2;" : "=r"(lo), "=r"(hi) : "l"(v));
    return __uint_as_float(lo) + __uint_as_float(hi);
}
__device__ __forceinline__ float fsig(float x) {
    return __fdividef(1.0f, 1.0f + __expf(-x));
}
__device__ __forceinline__ float ftanh(float x) {
    return __fdividef(2.0f, 1.0f + __expf(-2.0f * x)) - 1.0f;
}

#define FMA2B4(base, wreg, a0, a1, a2, a3)                                    \
    f2(acc[(base)+0], (wreg).x, (a0).x); f2(acc[(base)+0], (wreg).y, (a0).y); \
    f2(acc[(base)+1], (wreg).x, (a1).x); f2(acc[(base)+1], (wreg).y, (a1).y); \
    f2(acc[(base)+2], (wreg).x, (a2).x); f2(acc[(base)+2], (wreg).y, (a2).y); \
    f2(acc[(base)+3], (wreg).x, (a3).x); f2(acc[(base)+3], (wreg).y, (a3).y);

// one matrix, 8 gate rows (2 units x 4 gates), 4 batches, 7 k-chunks
__device__ __forceinline__ void dot8(const float* __restrict__ wb,
                                     const float* __restrict__ ha,
                                     ull* acc)
{
    #pragma unroll
    for (int c = 0; c < 7; c++) {
        ulonglong2 a0 = *(const ulonglong2*)(ha + 0 * ABST + c * 4);
        ulonglong2 a1 = *(const ulonglong2*)(ha + 1 * ABST + c * 4);
        ulonglong2 a2 = *(const ulonglong2*)(ha + 2 * ABST + c * 4);
        ulonglong2 a3 = *(const ulonglong2*)(ha + 3 * ABST + c * 4);
        #pragma unroll
        for (int g = 0; g < 4; g++) {
            ulonglong2 wA = *(const ulonglong2*)(wb + g * GST + 0 * MROW + c * 4);
            ulonglong2 wB = *(const ulonglong2*)(wb + g * GST + 1 * MROW + c * 4);
            FMA2B4((g * 2 + 0) * 4, wA, a0, a1, a2, a3);
            FMA2B4((g * 2 + 1) * 4, wB, a0, a1, a2, a3);
        }
    }
}

// reduce 32 accs -> 8 rows x own-2-batches pre-acts
#define REDUCE32()                                                  \
    float s[32];                                                    \
    _Pragma("unroll") for (int ii = 0; ii < 32; ii++) s[ii] = hadd(acc[ii]); \
    float p0[8], p1[8];                                             \
    _Pragma("unroll") for (int r = 0; r < 8; r++) {                 \
        float oa = kh ? s[r*4+2] : s[r*4+0];                        \
        float ob = kh ? s[r*4+3] : s[r*4+1];                        \
        float xa = kh ? s[r*4+0] : s[r*4+2];                        \
        float xb = kh ? s[r*4+1] : s[r*4+3];                        \
        p0[r] = oa + __shfl_xor_sync(mask, xa, 1);                  \
        p1[r] = ob + __shfl_xor_sync(mask, xb, 1);                  \
    }

// LSTM cells for 2 units x own 2 batches; rows r = g*2+u; writes h to hd
#define CELLS(hd)                                                             \
    _Pragma("unroll") for (int u = 0; u < 2; u++) {                           \
        float pi0 = p0[0+u] + bs[0+u], pi1 = p1[0+u] + bs[0+u];               \
        float pf0 = p0[2+u] + bs[2+u], pf1 = p1[2+u] + bs[2+u];               \
        float pg0 = p0[4+u] + bs[4+u], pg1 = p1[4+u] + bs[4+u];               \
        float po0 = p0[6+u] + bs[6+u], po1 = p1[6+u] + bs[6+u];               \
        cs[u*2+0] = fsig(pf0) * cs[u*2+0] + fsig(pi0) * ftanh(pg0);           \
        cs[u*2+1] = fsig(pf1) * cs[u*2+1] + fsig(pi1) * ftanh(pg1);           \
        (hd)[ob0 * ABST + ju0 + u] = fsig(po0) * ftanh(cs[u*2+0]);            \
        (hd)[ob1 * ABST + ju0 + u] = fsig(po1) * ftanh(cs[u*2+1]);            \
    }

__global__ void __launch_bounds__(NT, 1) lstm_pers(
    const float* __restrict__ xin,  const float* __restrict__ tin,
    const float* __restrict__ Wih0, const float* __restrict__ Whh0,
    const float* __restrict__ bih0, const float* __restrict__ bhh0,
    const float* __restrict__ Wih1, const float* __restrict__ Whh1,
    const float* __restrict__ bih1, const float* __restrict__ bhh1,
    const float* __restrict__ Wih2, const float* __restrict__ Whh2,
    const float* __restrict__ bih2, const float* __restrict__ bhh2,
    const float* __restrict__ Wlin, const float* __restrict__ blin,
    float* __restrict__ out)
{
    extern __shared__ float sm[];
    const int tid   = threadIdx.x;
    const int bbase = blockIdx.x * NBb;

    // ---- one-time staging: padded matrices (unit 51 and col 51 = 0) ----
    {
        const float* srcs[5] = {Whh0, Wih1, Whh1, Wih2, Whh2};
        const int    dsts[5] = {O_WHH0, O_WIH1, O_WHH1, O_WIH2, O_WHH2};
        for (int w = 0; w < 5; w++) {
            const float* s = srcs[w];
            float*       d = sm + dsts[w];
            for (int i = tid; i < MSZ; i += NT) {
                int r = i / MROW, k = i - r * MROW;
                int g = r / HU,   j = r - g * HU;
                d[i] = (j < Hn && k < Hn) ? s[(g * Hn + j) * Hn + k] : 0.0f;
            }
        }
    }
    {
        const float* bi[3] = {bih0, bih1, bih2};
        const float* bh[3] = {bhh0, bhh1, bhh2};
        for (int i = tid; i < 3 * 208; i += NT) {
            int lay = i / 208, r = i - lay * 208;
            int g = r / HU, j = r - g * HU;
            sm[O_BIAS + i] = (j < Hn) ? (bi[lay][g*Hn+j] + bh[lay][g*Hn+j]) : 0.0f;
        }
    }
    for (int i = tid; i < 2 * MROW; i += NT) {
        int r = i / MROW, k = i - r * MROW;
        sm[O_WLIN + i] = (k < Hn) ? Wlin[r * Hn + k] : 0.0f;
    }
    if (tid < 2) sm[O_BLIN + tid] = blin[tid];
    for (int i = tid; i < 6 * HBUF; i += NT) sm[O_H + i] = 0.0f;

    const int wid = tid >> 5;
    const int grp = (wid < 4) ? 1 : (wid < 8) ? 2 : (wid < 12) ? 0 : 3;
    const int lt  = tid & 127;
    const bool on = (grp != 3) && (lt < 104);
    const int jp = lt >> 2, b4 = (lt >> 1) & 1, kh = lt & 1;
    const unsigned mask = ((lt >> 5) == 3) ? 0xFFu : 0xFFFFFFFFu;
    const int ko   = kh * 28;
    const int ju0  = 2 * jp;
    const int aoff = b4 * 4 * ABST + ko;
    const int ob0  = b4 * 4 + kh * 2, ob1 = ob0 + 1;

    // weight base pointers (row (g,u) at +g*GST + u*MROW)
    const float* w0b = sm + O_WHH0 + ju0 * MROW + ko;
    const float* wi1 = sm + O_WIH1 + ju0 * MROW + ko;
    const float* wh1 = sm + O_WHH1 + ju0 * MROW + ko;
    const float* wi2 = sm + O_WIH2 + ju0 * MROW + ko;
    const float* wh2 = sm + O_WHH2 + ju0 * MROW + ko;

    __syncthreads();   // weights staged (biases read below)

    // biases for own 8 rows
    float bs[8];
    #pragma unroll
    for (int r = 0; r < 8; r++)
        bs[r] = on ? sm[O_BIAS + grp * 208 + (r >> 1) * HU + ju0 + (r & 1)] : 0.0f;

    // L0 input weights (2 cols x 8 rows) in registers
    float wx[16];
    #pragma unroll
    for (int i = 0; i < 16; i++) wx[i] = 0.0f;
    if (grp == 0 && on) {
        #pragma unroll
        for (int u = 0; u < 2; u++) {
            int ju = ju0 + u;
            if (ju < Hn) {
                #pragma unroll
                for (int g = 0; g < 4; g++) {
                    wx[(u*4+g)*2+0] = Wih0[(g*Hn+ju)*2+0];
                    wx[(u*4+g)*2+1] = Wih0[(g*Hn+ju)*2+1];
                }
            }
        }
    }

    float cs[4] = {0.f, 0.f, 0.f, 0.f};   // 2 units x 2 batches cell state

    for (int tk = 0; tk <= Tn + 2; tk++) {
        __syncthreads();                      // tick barrier: prev h visible
        if ((tk & 15) == 0 && tk < Tn) {      // stage inputs for t = tk..tk+15
            if (tid < 256) {
                int tt = tid >> 4, col = tid & 15;
                float v;
                if (col < 8) v = xin[(size_t)(bbase + col) * Tn + tk + tt];
                else         v = tin[(size_t)(bbase + col - 8) * Tn + tk + tt];
                sm[O_XS + tid] = v;
            }
            __syncthreads();
        }
        const int pr = tk & 1, po = pr ^ 1;

        if (grp == 1) {                       // layer 1, t = tk-1
            if (on && tk >= 1 && tk <= Tn) {
                ull acc[32];
                #pragma unroll
                for (int ii = 0; ii < 32; ii++) acc[ii] = 0ull;
                dot8(wi1, sm + O_H + (0*2 + po) * HBUF + aoff, acc);  // x = h0(t)
                dot8(wh1, sm + O_H + (1*2 + pr) * HBUF + aoff, acc);  // h1(t-1)
                REDUCE32();
                CELLS(sm + O_H + (1*2 + po) * HBUF);
            }
        } else if (grp == 2) {                // layer 2, t = tk-2
            if (on && tk >= 2 && tk <= Tn + 1) {
                ull acc[32];
                #pragma unroll
                for (int ii = 0; ii < 32; ii++) acc[ii] = 0ull;
                dot8(wi2, sm + O_H + (1*2 + pr) * HBUF + aoff, acc);  // x = h1(t)
                dot8(wh2, sm + O_H + (2*2 + po) * HBUF + aoff, acc);  // h2(t-1)
                REDUCE32();
                CELLS(sm + O_H + (2*2 + pr) * HBUF);
            }
        } else if (grp == 0) {                // layer 0, t = tk
            if (on && tk < Tn) {
                const int tc = tk & 15;
                ull acc[32];
                #pragma unroll
                for (int ii = 0; ii < 32; ii++) acc[ii] = 0ull;
                dot8(w0b, sm + O_H + (0*2 + po) * HBUF + aoff, acc);  // h0(t-1)
                REDUCE32();
                float xv0 = sm[O_XS + tc*16 + ob0], xv1 = sm[O_XS + tc*16 + ob1];
                float tv0 = sm[O_XS + tc*16 + 8 + ob0], tv1 = sm[O_XS + tc*16 + 8 + ob1];
                #pragma unroll
                for (int r = 0; r < 8; r++) {
                    int u = r & 1, g = r >> 1;
                    p0[r] += wx[(u*4+g)*2] * xv0 + wx[(u*4+g)*2+1] * tv0;
                    p1[r] += wx[(u*4+g)*2] * xv1 + wx[(u*4+g)*2+1] * tv1;
                }
                CELLS(sm + O_H + (0*2 + pr) * HBUF);
            }
        } else {                              // head, t = tk-3
            int lane = tid & 31;
            if (lane < 16 && tk >= 3) {
                int t = tk - 3;
                int bb = lane >> 1, o = lane & 1;
                const float* hh = sm + O_H + (2*2 + ((t & 1))) * HBUF + bb * ABST;
                const float* w  = sm + O_WLIN + o * MROW;
                float ssum = sm[O_BLIN + o];
                #pragma unroll
                for (int k = 0; k < Hn; k++) ssum += w[k] * hh[k];
                if (o) ssum = (ssum > 30.0f) ? ssum : log1pf(expf(ssum));
                out[(((size_t)(bbase + bb)) * Tn + (size_t)t) * 2 + o] = ssum;
            }
        }
    }
}

extern "C" void kernel_launch(void* const* d_in, const int* in_sizes, int n_in,
                              void* d_out, int out_size)
{
    (void)in_sizes; (void)n_in; (void)out_size;
    cudaFuncSetAttribute(lstm_pers, cudaFuncAttributeMaxDynamicSharedMemorySize,
                         SM_BYTES);
    lstm_pers<<<NCTA, NT, SM_BYTES>>>(
        (const float*)d_in[0],  (const float*)d_in[1],
        (const float*)d_in[2],  (const float*)d_in[3],
        (const float*)d_in[4],  (const float*)d_in[5],
        (const float*)d_in[6],  (const float*)d_in[7],
        (const float*)d_in[8],  (const float*)d_in[9],
        (const float*)d_in[10], (const float*)d_in[11],
        (const float*)d_in[12], (const float*)d_in[13],
        (const float*)d_in[14], (const float*)d_in[15],
        (float*)d_out);
}

// round 12
// speedup vs baseline: 1.5311x; 1.0770x over previous
#include <cuda_runtime.h>
#include <math.h>

// ---------------------------------------------------------------------------
// 3-layer LSTM (H=51) + linear(2) head, B=1024, T=2048, persistent kernel.
// LAYER-PIPELINED, fine-grain threads: 128 CTAs x 672 threads (21 warps):
//   warps 0-7  : layer-1 group (208 act. threads), computes t = tk-1
//   warps 8-15 : layer-2 group (208 act. threads), computes t = tk-2
//   warps 16-19: layer-0 group (104 act. threads), computes t = tk
//   warp  20   : linear head, computes t = tk-3
// ONE __syncthreads per tick. Thread = 1 unit x 4 gates, full K (no shfl
// reduction): g1/g2 threads own 2 batches (8 u64 accs), g0 threads own 4
// batches (16 accs). fma.rn.f32x2 k-pairs. H padded 51->52 (zero wt/bias).
// ---------------------------------------------------------------------------

#define Hn    51
#define HU    52                 // padded units
#define Tn    2048
#define NBb   8
#define NCTA  128
#define NT    672
#define ABST  60                 // act batch-row stride (floats)
#define HBUF  480                // 8 * ABST
#define MROW  52                 // floats per weight row
#define MSZ   (208 * MROW)       // 10816 floats per padded matrix
#define GST   (HU * MROW)        // 2704: gate-block stride

// SMEM float offsets
#define O_WHH0 0
#define O_WIH1 10816
#define O_WHH1 21632
#define O_WIH2 32448
#define O_WHH2 43264
#define O_BIAS 54080             // [3][208]
#define O_WLIN 54704             // [2][52]
#define O_BLIN 54808             // 2 (+2 pad)
#define O_H    54812             // 6 bufs * 480 (O_H*4 % 16 == 0)
#define O_XS   57692             // [16][16]
#define SM_FLOATS 57948
#define SM_BYTES  (SM_FLOATS * 4)   // 231792 <= 232448

typedef unsigned long long ull;

__device__ __forceinline__ void f2(ull& a, ull w, ull v) {
    asm("fma.rn.f32x2 %0, %1, %2, %0;" : "+l"(a) : "l"(w), "l"(v));
}
__device__ __forceinline__ float hadd(ull v) {
    unsigned lo, hi;
    asm("mov.b64 {%0,%1}, %2;" : "=r"(lo), "=r"(hi) : "l"(v));
    return __uint_as_float(lo) + __uint_as_float(hi);
}
__device__ __forceinline__ float fsig(float x) {
    return __fdividef(1.0f, 1.0f + __expf(-x));
}
__device__ __forceinline__ float ftanh(float x) {
    return __fdividef(2.0f, 1.0f + __expf(-2.0f * x)) - 1.0f;
}

__global__ void __launch_bounds__(NT, 1) lstm_pers(
    const float* __restrict__ xin,  const float* __restrict__ tin,
    const float* __restrict__ Wih0, const float* __restrict__ Whh0,
    const float* __restrict__ bih0, const float* __restrict__ bhh0,
    const float* __restrict__ Wih1, const float* __restrict__ Whh1,
    const float* __restrict__ bih1, const float* __restrict__ bhh1,
    const float* __restrict__ Wih2, const float* __restrict__ Whh2,
    const float* __restrict__ bih2, const float* __restrict__ bhh2,
    const float* __restrict__ Wlin, const float* __restrict__ blin,
    float* __restrict__ out)
{
    extern __shared__ float sm[];
    const int tid   = threadIdx.x;
    const int bbase = blockIdx.x * NBb;

    // ---- one-time staging: padded matrices (unit 51 and col 51 = 0) ----
    {
        const float* srcs[5] = {Whh0, Wih1, Whh1, Wih2, Whh2};
        const int    dsts[5] = {O_WHH0, O_WIH1, O_WHH1, O_WIH2, O_WHH2};
        for (int w = 0; w < 5; w++) {
            const float* s = srcs[w];
            float*       d = sm + dsts[w];
            for (int i = tid; i < MSZ; i += NT) {
                int r = i / MROW, k = i - r * MROW;
                int g = r / HU,   j = r - g * HU;
                d[i] = (j < Hn && k < Hn) ? s[(g * Hn + j) * Hn + k] : 0.0f;
            }
        }
    }
    {
        const float* bi[3] = {bih0, bih1, bih2};
        const float* bh[3] = {bhh0, bhh1, bhh2};
        for (int i = tid; i < 3 * 208; i += NT) {
            int lay = i / 208, r = i - lay * 208;
            int g = r / HU, j = r - g * HU;
            sm[O_BIAS + i] = (j < Hn) ? (bi[lay][g*Hn+j] + bh[lay][g*Hn+j]) : 0.0f;
        }
    }
    for (int i = tid; i < 2 * MROW; i += NT) {
        int r = i / MROW, k = i - r * MROW;
        sm[O_WLIN + i] = (k < Hn) ? Wlin[r * Hn + k] : 0.0f;
    }
    if (tid < 2) sm[O_BLIN + tid] = blin[tid];
    for (int i = tid; i < 6 * HBUF; i += NT) sm[O_H + i] = 0.0f;

    const int wid = tid >> 5;
    int grp, lt;
    if (wid < 8)       { grp = 1; lt = tid; }
    else if (wid < 16) { grp = 2; lt = tid - 256; }
    else if (wid < 20) { grp = 0; lt = tid - 512; }
    else               { grp = 3; lt = tid - 640; }

    // thread coordinates
    int j, ob0, nb;
    if (grp == 1 || grp == 2) { j = lt >> 2; ob0 = (lt & 3) * 2; nb = 2; }
    else if (grp == 0)        { j = lt >> 1; ob0 = (lt & 1) * 4; nb = 4; }
    else                      { j = 0; ob0 = 0; nb = 0; }
    const bool on = (grp != 3) && (j < HU);
    const int act0 = ob0 * ABST;

    // weight row base pointers (gate g at + g*GST)
    const float* wmA;
    const float* wmB;
    if (grp == 1)      { wmA = sm + O_WIH1 + j * MROW; wmB = sm + O_WHH1 + j * MROW; }
    else if (grp == 2) { wmA = sm + O_WIH2 + j * MROW; wmB = sm + O_WHH2 + j * MROW; }
    else               { wmA = sm + O_WHH0 + j * MROW; wmB = wmA; }

    __syncthreads();   // weights + biases staged

    float bsv[4];
    #pragma unroll
    for (int g = 0; g < 4; g++)
        bsv[g] = on ? sm[O_BIAS + grp * 208 + g * HU + j] : 0.0f;

    // L0 input weights (2 cols x 4 gates) in registers
    float wx[8];
    #pragma unroll
    for (int i = 0; i < 8; i++) wx[i] = 0.0f;
    if (grp == 0 && on && j < Hn) {
        #pragma unroll
        for (int g = 0; g < 4; g++) {
            wx[g*2+0] = Wih0[(g*Hn + j)*2 + 0];
            wx[g*2+1] = Wih0[(g*Hn + j)*2 + 1];
        }
    }

    float cs0 = 0.f, cs1 = 0.f, cs2 = 0.f, cs3 = 0.f;

    for (int tk = 0; tk <= Tn + 2; tk++) {
        __syncthreads();                      // tick barrier: prev h visible
        if ((tk & 15) == 0 && tk < Tn) {      // stage inputs for t = tk..tk+15
            if (tid < 256) {
                int tt = tid >> 4, col = tid & 15;
                float v;
                if (col < 8) v = xin[(size_t)(bbase + col) * Tn + tk + tt];
                else         v = tin[(size_t)(bbase + col - 8) * Tn + tk + tt];
                sm[O_XS + tid] = v;
            }
            __syncthreads();
        }
        const int pr = tk & 1, po = pr ^ 1;

        if (grp == 1 || grp == 2) {
            const bool run = on && ((grp == 1) ? (tk >= 1 && tk <= Tn)
                                               : (tk >= 2 && tk <= Tn + 1));
            if (run) {
                const float* xa;  const float* ha;  float* hd;
                if (grp == 1) {   // layer 1, t = tk-1: x=h0(t), h=h1(t-1)
                    xa = sm + O_H + (0*2 + po) * HBUF;
                    ha = sm + O_H + (1*2 + pr) * HBUF;
                    hd = sm + O_H + (1*2 + po) * HBUF;
                } else {          // layer 2, t = tk-2: x=h1(t), h=h2(t-1)
                    xa = sm + O_H + (1*2 + pr) * HBUF;
                    ha = sm + O_H + (2*2 + po) * HBUF;
                    hd = sm + O_H + (2*2 + pr) * HBUF;
                }
                xa += act0; ha += act0;
                ull acc[8];
                #pragma unroll
                for (int ii = 0; ii < 8; ii++) acc[ii] = 0ull;
                #pragma unroll
                for (int c = 0; c < 13; c++) {
                    ulonglong2 x0 = *(const ulonglong2*)(xa + c*4);
                    ulonglong2 x1 = *(const ulonglong2*)(xa + ABST + c*4);
                    ulonglong2 h0 = *(const ulonglong2*)(ha + c*4);
                    ulonglong2 h1 = *(const ulonglong2*)(ha + ABST + c*4);
                    #pragma unroll
                    for (int g = 0; g < 4; g++) {
                        ulonglong2 wi = *(const ulonglong2*)(wmA + g*GST + c*4);
                        ulonglong2 wh = *(const ulonglong2*)(wmB + g*GST + c*4);
                        f2(acc[g*2+0], wi.x, x0.x); f2(acc[g*2+0], wi.y, x0.y);
                        f2(acc[g*2+1], wi.x, x1.x); f2(acc[g*2+1], wi.y, x1.y);
                        f2(acc[g*2+0], wh.x, h0.x); f2(acc[g*2+0], wh.y, h0.y);
                        f2(acc[g*2+1], wh.x, h1.x); f2(acc[g*2+1], wh.y, h1.y);
                    }
                }
                float p[8];
                #pragma unroll
                for (int ii = 0; ii < 8; ii++)
                    p[ii] = hadd(acc[ii]) + bsv[ii >> 1];
                float iv0 = fsig(p[0]),  iv1 = fsig(p[1]);
                float fv0 = fsig(p[2]),  fv1 = fsig(p[3]);
                float gv0 = ftanh(p[4]), gv1 = ftanh(p[5]);
                float ov0 = fsig(p[6]),  ov1 = fsig(p[7]);
                cs0 = fv0 * cs0 + iv0 * gv0;
                cs1 = fv1 * cs1 + iv1 * gv1;
                hd[(ob0 + 0) * ABST + j] = ov0 * ftanh(cs0);
                hd[(ob0 + 1) * ABST + j] = ov1 * ftanh(cs1);
            }
        } else if (grp == 0) {                // layer 0, t = tk
            if (on && tk < Tn) {
                const int tc = tk & 15;
                const float* ha = sm + O_H + (0*2 + po) * HBUF + act0;  // h0(t-1)
                float*       hd = sm + O_H + (0*2 + pr) * HBUF;
                ull acc[16];
                #pragma unroll
                for (int ii = 0; ii < 16; ii++) acc[ii] = 0ull;
                #pragma unroll
                for (int c = 0; c < 13; c++) {
                    ulonglong2 a0 = *(const ulonglong2*)(ha + 0*ABST + c*4);
                    ulonglong2 a1 = *(const ulonglong2*)(ha + 1*ABST + c*4);
                    ulonglong2 a2 = *(const ulonglong2*)(ha + 2*ABST + c*4);
                    ulonglong2 a3 = *(const ulonglong2*)(ha + 3*ABST + c*4);
                    #pragma unroll
                    for (int g = 0; g < 4; g++) {
                        ulonglong2 w = *(const ulonglong2*)(wmA + g*GST + c*4);
                        f2(acc[g*4+0], w.x, a0.x); f2(acc[g*4+0], w.y, a0.y);
                        f2(acc[g*4+1], w.x, a1.x); f2(acc[g*4+1], w.y, a1.y);
                        f2(acc[g*4+2], w.x, a2.x); f2(acc[g*4+2], w.y, a2.y);
                        f2(acc[g*4+3], w.x, a3.x); f2(acc[g*4+3], w.y, a3.y);
                    }
                }
                float xv[4], tv[4];
                #pragma unroll
                for (int i = 0; i < 4; i++) {
                    xv[i] = sm[O_XS + tc*16 + ob0 + i];
                    tv[i] = sm[O_XS + tc*16 + 8 + ob0 + i];
                }
                float p[16];
                #pragma unroll
                for (int g = 0; g < 4; g++)
                    #pragma unroll
                    for (int i = 0; i < 4; i++)
                        p[g*4+i] = hadd(acc[g*4+i]) + bsv[g]
                                 + wx[g*2]*xv[i] + wx[g*2+1]*tv[i];
                float ncs[4];
                #pragma unroll
                for (int i = 0; i < 4; i++) {
                    float cold = (i==0)?cs0:(i==1)?cs1:(i==2)?cs2:cs3;
                    float cn = fsig(p[4+i]) * cold + fsig(p[0+i]) * ftanh(p[8+i]);
                    ncs[i] = cn;
                    hd[(ob0 + i) * ABST + j] = fsig(p[12+i]) * ftanh(cn);
                }
                cs0 = ncs[0]; cs1 = ncs[1]; cs2 = ncs[2]; cs3 = ncs[3];
            }
        } else {                              // head, t = tk-3
            int lane = lt & 31;
            if (lane < 16 && tk >= 3) {
                int t = tk - 3;
                int bb = lane >> 1, o = lane & 1;
                const float* hh = sm + O_H + (2*2 + (t & 1)) * HBUF + bb * ABST;
                const float* w  = sm + O_WLIN + o * MROW;
                float ssum = sm[O_BLIN + o];
                #pragma unroll
                for (int k = 0; k < Hn; k++) ssum += w[k] * hh[k];
                if (o) ssum = (ssum > 30.0f) ? ssum : log1pf(expf(ssum));
                out[(((size_t)(bbase + bb)) * Tn + (size_t)t) * 2 + o] = ssum;
            }
        }
    }
}

extern "C" void kernel_launch(void* const* d_in, const int* in_sizes, int n_in,
                              void* d_out, int out_size)
{
    (void)in_sizes; (void)n_in; (void)out_size;
    cudaFuncSetAttribute(lstm_pers, cudaFuncAttributeMaxDynamicSharedMemorySize,
                         SM_BYTES);
    lstm_pers<<<NCTA, NT, SM_BYTES>>>(
        (const float*)d_in[0],  (const float*)d_in[1],
        (const float*)d_in[2],  (const float*)d_in[3],
        (const float*)d_in[4],  (const float*)d_in[5],
        (const float*)d_in[6],  (const float*)d_in[7],
        (const float*)d_in[8],  (const float*)d_in[9],
        (const float*)d_in[10], (const float*)d_in[11],
        (const float*)d_in[12], (const float*)d_in[13],
        (const float*)d_in[14], (const float*)d_in[15],
        (float*)d_out);
}